// round 14
// baseline (speedup 1.0000x reference)
#include <cuda_runtime.h>
#include <cuda_fp16.h>
#include <cstdint>
#include <math.h>

#define NB     128
#define NT     32
#define ND     1024
#define NADA   1024
#define NINTER 1024
#define NRANK  8
#define GK     1024
#define BM     128
#define BK     32
#define SRA    80            // A row: 32 halves (64B) + 16B pad
#define ATILE  (128 * SRA)   // 10240
#define SRB32  528           // B fp32 row: 512B + 16B pad
#define B32TILE (32 * SRB32) // 16896
#define STG32  (ATILE + B32TILE)  // 27136
#define KSPLIT 8
#define NW2    (2 * ND * NRANK)   // 16384

// ---- P via tensor cores ----
#define PCHUNKS 4
#define PCD     256
#define PSZ     (NB * NT * NRANK)
#define XS_STRIDE 528
#define XA_PAD  12

// ---- final GEMM ----
#define FBK    64
#define FNIT   (GK / FBK)
#define FSRA   144
#define FSRB   272
#define FATILE (128 * FSRA)
#define FBTILE (64 * FSRB)
#define FSTAGE (FATILE + FBTILE)
#define FSMEM  (3 * FSTAGE)

// ---------------- scratch ----------------------------------------------------
__device__ __half g_ae[NB * NADA];
__device__ __half g_h[NB * NINTER];
__device__ __half g_x16[NB * NT * ND];
__device__ __half g_base16[ND * ND];
__device__ __half g_hpart16[KSPLIT * NB * NINTER];
__device__ float  g_xwpart[2 * NB * NW2];
__device__ float  g_Ppart[PCHUNKS * PSZ];

// ---------------- PTX helpers -------------------------------------------------
__device__ __forceinline__ uint32_t smem_u32(const void* p) {
    uint32_t a;
    asm("{ .reg .u64 t; cvta.to.shared.u64 t, %1; cvt.u32.u64 %0, t; }" : "=r"(a) : "l"(p));
    return a;
}
#define CP16(sa, ga) \
    asm volatile("cp.async.cg.shared.global [%0], [%1], 16;" :: "r"(sa), "l"(ga))
#define CP_COMMIT() asm volatile("cp.async.commit_group;")
#define CP_WAIT(n)  asm volatile("cp.async.wait_group %0;" :: "n"(n))
#define LDSM4(r, addr) \
    asm volatile("ldmatrix.sync.aligned.m8n8.x4.shared.b16 {%0,%1,%2,%3}, [%4];" \
        : "=r"((r)[0]), "=r"((r)[1]), "=r"((r)[2]), "=r"((r)[3]) : "r"(addr))
#define LDSM4T(r, addr) \
    asm volatile("ldmatrix.sync.aligned.m8n8.x4.trans.shared.b16 {%0,%1,%2,%3}, [%4];" \
        : "=r"((r)[0]), "=r"((r)[1]), "=r"((r)[2]), "=r"((r)[3]) : "r"(addr))
#define MMA_F16(d, a, b0, b1) \
    asm volatile("mma.sync.aligned.m16n8k16.row.col.f32.f16.f16.f32 " \
        "{%0,%1,%2,%3},{%4,%5,%6,%7},{%8,%9},{%0,%1,%2,%3};" \
        : "+f"((d)[0]), "+f"((d)[1]), "+f"((d)[2]), "+f"((d)[3]) \
        : "r"((a)[0]), "r"((a)[1]), "r"((a)[2]), "r"((a)[3]), "r"(b0), "r"(b1))

__device__ __forceinline__ float gelu_exact(float v) {
    return 0.5f * v * (1.0f + erff(v * 0.70710678118654752f));
}

// ---------------- layernorm (writes fp16) -------------------------------------
__global__ __launch_bounds__(256) void ln_kernel(
    const float* __restrict__ ada, const float* __restrict__ gamma,
    const float* __restrict__ beta, __half* __restrict__ outh)
{
    int row = blockIdx.x;
    const float4 v = reinterpret_cast<const float4*>(ada + (size_t)row * NADA)[threadIdx.x];
    float s  = v.x + v.y + v.z + v.w;
    float ss = v.x * v.x + v.y * v.y + v.z * v.z + v.w * v.w;
    __shared__ float rs[8], rq[8];
    #pragma unroll
    for (int o = 16; o > 0; o >>= 1) {
        s  += __shfl_xor_sync(0xFFFFFFFFu, s, o);
        ss += __shfl_xor_sync(0xFFFFFFFFu, ss, o);
    }
    int warp = threadIdx.x >> 5, lane = threadIdx.x & 31;
    if (lane == 0) { rs[warp] = s; rq[warp] = ss; }
    __syncthreads();
    float sum = 0.f, sumsq = 0.f;
    #pragma unroll
    for (int i = 0; i < 8; i++) { sum += rs[i]; sumsq += rq[i]; }
    const float inv_n = 1.0f / NADA;
    float mu = sum * inv_n;
    float rstd = rsqrtf(sumsq * inv_n - mu * mu + 1e-5f);
    const float4 gv = reinterpret_cast<const float4*>(gamma)[threadIdx.x];
    const float4 bv = reinterpret_cast<const float4*>(beta)[threadIdx.x];
    float o0 = (v.x - mu) * rstd * gv.x + bv.x;
    float o1 = (v.y - mu) * rstd * gv.y + bv.y;
    float o2 = (v.z - mu) * rstd * gv.z + bv.z;
    float o3 = (v.w - mu) * rstd * gv.w + bv.w;
    __half2 hh[2] = { __floats2half2_rn(o0, o1), __floats2half2_rn(o2, o3) };
    *reinterpret_cast<uint2*>(outh + (size_t)row * NADA + threadIdx.x * 4) =
        *reinterpret_cast<uint2*>(hh);
}

// ---------------- reduce fp16 split-K partials + bias + GELU -> fp16 ----------
__global__ __launch_bounds__(256) void reduce_gelu16_kernel(
    const __half2* __restrict__ part, const float* __restrict__ b1,
    __half* __restrict__ h)
{
    int i = blockIdx.x * 256 + threadIdx.x;
    float sx = 0.f, sy = 0.f;
    #pragma unroll
    for (int z = 0; z < KSPLIT; z++) {
        float2 f = __half22float2(part[(size_t)z * (NB * NINTER / 2) + i]);
        sx += f.x; sy += f.y;
    }
    const float2 bb = *reinterpret_cast<const float2*>(b1 + ((2 * i) & (NINTER - 1)));
    *reinterpret_cast<__half2*>(h + (size_t)i * 2) =
        __floats2half2_rn(gelu_exact(sx + bb.x), gelu_exact(sy + bb.y));
}

// ---------------- P via tensor cores (xa = part0 + part1 + b2) ----------------
__global__ __launch_bounds__(256) void p_mma_kernel(
    const __half* __restrict__ x16, const float* __restrict__ xwpart,
    const float* __restrict__ b2, float* __restrict__ Pp)
{
    __shared__ __align__(16) char xs[NT * XS_STRIDE];
    __shared__ float xa[PCD * XA_PAD];
    int b = blockIdx.x, cch = blockIdx.y;
    int tid = threadIdx.x;

    #pragma unroll
    for (int i = 0; i < 4; i++) {
        int c = tid + i * 256;
        int t = c >> 5, seg = c & 31;
        *reinterpret_cast<uint4*>(xs + t * XS_STRIDE + seg * 16) =
            *reinterpret_cast<const uint4*>(x16 + ((size_t)b * NT + t) * ND + cch * PCD + seg * 8);
    }
    int obase = cch * PCD * NRANK;
    const float* p0 = xwpart + (size_t)b * NW2 + obase;
    const float* p1 = xwpart + (size_t)NB * NW2 + (size_t)b * NW2 + obase;
    #pragma unroll
    for (int i = 0; i < 8; i++) {
        int idx = tid + i * 256;
        int d = idx >> 3, r = idx & 7;
        xa[d * XA_PAD + r] = p0[idx] + p1[idx] + b2[obase + idx];
    }
    __syncthreads();

    if (tid < 32) {
        int lane = tid;
        float acc[2][4];
        #pragma unroll
        for (int mt = 0; mt < 2; mt++)
            #pragma unroll
            for (int e = 0; e < 4; e++) acc[mt][e] = 0.f;

        uint32_t sxs = smem_u32(xs);
        const int a_row = lane & 15;
        const int a_off = (lane >> 4) * 16;
        const int b_n   = lane >> 2;
        const int b_kp  = (lane & 3) * 2;

        #pragma unroll
        for (int ks = 0; ks < PCD / 16; ks++) {
            uint32_t af[2][4];
            LDSM4(af[0], sxs + a_row * XS_STRIDE + ks * 32 + a_off);
            LDSM4(af[1], sxs + (16 + a_row) * XS_STRIDE + ks * 32 + a_off);
            int k0 = ks * 16 + b_kp;
            float f0 = xa[(k0 + 0) * XA_PAD + b_n];
            float f1 = xa[(k0 + 1) * XA_PAD + b_n];
            float f2 = xa[(k0 + 8) * XA_PAD + b_n];
            float f3 = xa[(k0 + 9) * XA_PAD + b_n];
            __half2 h01 = __floats2half2_rn(f0, f1);
            __half2 h23 = __floats2half2_rn(f2, f3);
            uint32_t b0 = *reinterpret_cast<uint32_t*>(&h01);
            uint32_t b1 = *reinterpret_cast<uint32_t*>(&h23);
            MMA_F16(acc[0], af[0], b0, b1);
            MMA_F16(acc[1], af[1], b0, b1);
        }

        float* pdst = Pp + (size_t)cch * PSZ + (size_t)b * NT * NRANK;
        #pragma unroll
        for (int mt = 0; mt < 2; mt++) {
            int row = mt * 16 + (lane >> 2);
            int col = (lane & 3) * 2;
            *reinterpret_cast<float2*>(pdst + row * NRANK + col) =
                make_float2(acc[mt][0], acc[mt][1]);
            *reinterpret_cast<float2*>(pdst + (row + 8) * NRANK + col) =
                make_float2(acc[mt][2], acc[mt][3]);
        }
    }
}

// ---------------- pipelined GEMM, A fp16 + B fp32 (cvt in fragment load) ------
// MODE 0 (G1): split-K fp16 partials; blocks x>=GEMMBX carry fused x/base cvt.
// MODE 2 (G2): split-K fp32 partials.
template<int MODE, int NIT, int NSTGt, int LA, int MAXBLK, int GEMMBX>
__global__ __launch_bounds__(256, MAXBLK) void pipe_gemm32_kernel(
    const __half* __restrict__ A, const float* __restrict__ B, int N,
    float* __restrict__ outf, __half* __restrict__ outh,
    const float4* __restrict__ srcx, __half* __restrict__ dstx, int n4x,
    const float4* __restrict__ srcb, __half* __restrict__ dstb, int n4tot)
{
    if (MODE == 0 && (int)blockIdx.x >= GEMMBX) {
        if (blockIdx.z != 0) return;
        int stride = (gridDim.x - GEMMBX) * 256;
        for (int i = ((int)blockIdx.x - GEMMBX) * 256 + (int)threadIdx.x;
             i < n4tot; i += stride) {
            const float4* s; __half* d; int j;
            if (i < n4x) { s = srcx; d = dstx; j = i; }
            else         { s = srcb; d = dstb; j = i - n4x; }
            float4 v = s[j];
            __half2 hh[2] = { __floats2half2_rn(v.x, v.y), __floats2half2_rn(v.z, v.w) };
            *reinterpret_cast<uint2*>(d + (size_t)j * 4) = *reinterpret_cast<uint2*>(hh);
        }
        return;
    }

    extern __shared__ char smem[];
    const int tid = threadIdx.x, wid = tid >> 5, lane = tid & 31;
    const int m0 = blockIdx.y * BM, n0 = blockIdx.x * 128;
    const int kb = blockIdx.z * (NIT * BK);
    const int wm = wid & 1, wn = wid >> 1;
    const uint32_t sb = smem_u32(smem);

    float acc[4][4][4];
    #pragma unroll
    for (int i = 0; i < 4; i++)
        #pragma unroll
        for (int j = 0; j < 4; j++)
            #pragma unroll
            for (int e = 0; e < 4; e++) acc[i][j][e] = 0.f;

    auto issue = [&](int c) {
        uint32_t st = sb + (c % NSTGt) * STG32;
        int k0 = kb + c * BK;
        #pragma unroll
        for (int i = 0; i < 2; i++) {
            int ch = tid + i * 256, r = ch >> 2, cc = ch & 3;
            CP16(st + r * SRA + cc * 16, A + (size_t)(m0 + r) * GK + k0 + cc * 8);
        }
        #pragma unroll
        for (int i = 0; i < 4; i++) {
            int ch = tid + i * 256, r = ch >> 5, cc = ch & 31;
            CP16(st + ATILE + r * SRB32 + cc * 16, B + (size_t)(k0 + r) * N + n0 + cc * 4);
        }
        CP_COMMIT();
    };

    const int a_row = wm * 64 + (lane & 15);
    const int a_off = (lane >> 4) * 16;
    const int b_n   = lane >> 2;
    const int b_kp  = (lane & 3) * 2;

    #pragma unroll
    for (int s = 0; s < LA && s < NIT; s++) issue(s);

    for (int c = 0; c < NIT; c++) {
        int rem = NIT - 1 - c;
        int cap = rem < (LA - 1) ? rem : (LA - 1);
        if (cap >= 3) CP_WAIT(3);
        else if (cap == 2) CP_WAIT(2);
        else if (cap == 1) CP_WAIT(1);
        else CP_WAIT(0);
        __syncthreads();
        if (c + LA < NIT) issue(c + LA);

        const char* bstg = smem + ((c % NSTGt) * STG32) + ATILE;
        uint32_t abase = sb + (c % NSTGt) * STG32;
        #pragma unroll
        for (int ks = 0; ks < 2; ks++) {
            uint32_t af[4][4];
            #pragma unroll
            for (int mt = 0; mt < 4; mt++)
                LDSM4(af[mt], abase + (a_row + mt * 16) * SRA + ks * 32 + a_off);
            #pragma unroll
            for (int nt = 0; nt < 4; nt++) {
                int ncol = wn * 32 + nt * 8 + b_n;
                const char* col = bstg + (size_t)ncol * 4;
                int r0 = ks * 16 + b_kp;
                float f0 = *reinterpret_cast<const float*>(col + (r0 + 0) * SRB32);
                float f1 = *reinterpret_cast<const float*>(col + (r0 + 1) * SRB32);
                float f2 = *reinterpret_cast<const float*>(col + (r0 + 8) * SRB32);
                float f3 = *reinterpret_cast<const float*>(col + (r0 + 9) * SRB32);
                __half2 h01 = __floats2half2_rn(f0, f1);
                __half2 h23 = __floats2half2_rn(f2, f3);
                uint32_t b0 = *reinterpret_cast<uint32_t*>(&h01);
                uint32_t b1 = *reinterpret_cast<uint32_t*>(&h23);
                #pragma unroll
                for (int mt = 0; mt < 4; mt++)
                    MMA_F16(acc[mt][nt], af[mt], b0, b1);
            }
        }
    }

    #pragma unroll
    for (int mt = 0; mt < 4; mt++) {
        int r_in0 = wm * 64 + mt * 16 + (lane >> 2);
        #pragma unroll
        for (int half = 0; half < 2; half++) {
            int m = m0 + r_in0 + half * 8;
            #pragma unroll
            for (int nt = 0; nt < 4; nt++) {
                int n = n0 + wn * 32 + nt * 8 + (lane & 3) * 2;
                float v0 = acc[mt][nt][half * 2 + 0];
                float v1 = acc[mt][nt][half * 2 + 1];
                if (MODE == 0) {
                    __half* po = outh + (size_t)blockIdx.z * (NB * NINTER);
                    *reinterpret_cast<__half2*>(po + (size_t)m * N + n) =
                        __floats2half2_rn(v0, v1);
                } else {
                    float* po = outf + (size_t)blockIdx.z * ((size_t)NB * NW2);
                    float2 o; o.x = v0; o.y = v1;
                    *reinterpret_cast<float2*>(po + (size_t)m * N + n) = o;
                }
            }
        }
    }
}

// ---------------- final GEMM: cp.async 3-stage, BK=64, fp16 x fp16 ------------
__global__ __launch_bounds__(256, 2) void gemm_final_kernel(
    const __half* __restrict__ A, const __half* __restrict__ B,
    float* __restrict__ outf, const float* __restrict__ xres,
    const float* __restrict__ Pp, const float* __restrict__ xwpart,
    const float* __restrict__ b2)
{
    extern __shared__ char smem[];
    const int tid = threadIdx.x, wid = tid >> 5, lane = tid & 31;
    const int m0 = blockIdx.y * BM, n0 = blockIdx.x * 128;
    const int wm = wid & 1, wn = wid >> 1;
    const uint32_t sb = smem_u32(smem);
    const int N = ND;

    float acc[4][4][4];
    #pragma unroll
    for (int i = 0; i < 4; i++)
        #pragma unroll
        for (int j = 0; j < 4; j++)
            #pragma unroll
            for (int e = 0; e < 4; e++) acc[i][j][e] = 0.f;

    auto issue = [&](int c) {
        uint32_t st = sb + (c % 3) * FSTAGE;
        int k0 = c * FBK;
        #pragma unroll
        for (int i = 0; i < 4; i++) {
            int ch = tid + i * 256, r = ch >> 3, cc = ch & 7;
            CP16(st + r * FSRA + cc * 16, A + (size_t)(m0 + r) * GK + k0 + cc * 8);
        }
        #pragma unroll
        for (int i = 0; i < 4; i++) {
            int ch = tid + i * 256, r = ch >> 4, cc = ch & 15;
            CP16(st + FATILE + r * FSRB + cc * 16, B + (size_t)(k0 + r) * N + n0 + cc * 8);
        }
        CP_COMMIT();
    };

    const int a_row  = wm * 64 + (lane & 15);
    const int a_off  = (lane >> 4) * 16;
    const int b_row  = lane & 15;
    const int b_colb = wn * 64 + (lane >> 4) * 16;

    issue(0);
    issue(1);

    for (int c = 0; c < FNIT; c++) {
        if (c < FNIT - 1) CP_WAIT(1); else CP_WAIT(0);
        __syncthreads();
        if (c + 2 < FNIT) issue(c + 2);

        uint32_t base = sb + (c % 3) * FSTAGE;
        #pragma unroll
        for (int ks = 0; ks < 4; ks++) {
            uint32_t af[4][4];
            #pragma unroll
            for (int mt = 0; mt < 4; mt++)
                LDSM4(af[mt], base + (a_row + mt * 16) * FSRA + ks * 32 + a_off);
            uint32_t bf[4][2];
            #pragma unroll
            for (int pr = 0; pr < 2; pr++) {
                uint32_t r[4];
                LDSM4T(r, base + FATILE + (ks * 16 + b_row) * FSRB + b_colb + pr * 32);
                bf[pr * 2 + 0][0] = r[0]; bf[pr * 2 + 0][1] = r[1];
                bf[pr * 2 + 1][0] = r[2]; bf[pr * 2 + 1][1] = r[3];
            }
            #pragma unroll
            for (int mt = 0; mt < 4; mt++)
                #pragma unroll
                for (int nt = 0; nt < 4; nt++)
                    MMA_F16(acc[mt][nt], af[mt], bf[nt][0], bf[nt][1]);
        }
    }
    __syncthreads();

    // epilogue: + xres + P @ x_b^T  (x_b = part0 + part1 + b2)
    float* Ps  = reinterpret_cast<float*>(smem);
    float* xbs = reinterpret_cast<float*>(smem + 4096);
    for (int i = tid; i < BM * NRANK; i += 256) {
        float sv = 0.f;
        #pragma unroll
        for (int c = 0; c < PCHUNKS; c++)
            sv += Pp[(size_t)c * PSZ + (size_t)m0 * NRANK + i];
        Ps[i] = sv;
    }
    for (int i = tid; i < 4 * 128 * NRANK; i += 256) {
        int g = i >> 10, j = (i >> 3) & 127, r = i & 7;
        int bg = (m0 >> 5) + g;
        int o = ND * NRANK + (n0 + j) * NRANK + r;
        size_t go = (size_t)bg * NW2 + o;
        xbs[i] = xwpart[go] + xwpart[(size_t)NB * NW2 + go] + b2[o];
    }
    __syncthreads();

    #pragma unroll
    for (int mt = 0; mt < 4; mt++) {
        int r_in0 = wm * 64 + mt * 16 + (lane >> 2);
        #pragma unroll
        for (int half = 0; half < 2; half++) {
            int r_in = r_in0 + half * 8;
            int m = m0 + r_in;
            int g = r_in >> 5;
            const float4* pr = reinterpret_cast<const float4*>(Ps + r_in * 8);
            float4 p0 = pr[0], p1 = pr[1];
            #pragma unroll
            for (int nt = 0; nt < 4; nt++) {
                int c_in = wn * 32 + nt * 8 + (lane & 3) * 2;
                int n = n0 + c_in;
                const float4* xb0 = reinterpret_cast<const float4*>(xbs + (g * 128 + c_in) * 8);
                const float4* xb1 = reinterpret_cast<const float4*>(xbs + (g * 128 + c_in + 1) * 8);
                float4 u0 = xb0[0], u1 = xb0[1], v0 = xb1[0], v1 = xb1[1];
                float e0 = p0.x * u0.x + p0.y * u0.y + p0.z * u0.z + p0.w * u0.w
                         + p1.x * u1.x + p1.y * u1.y + p1.z * u1.z + p1.w * u1.w;
                float e1 = p0.x * v0.x + p0.y * v0.y + p0.z * v0.z + p0.w * v0.w
                         + p1.x * v1.x + p1.y * v1.y + p1.z * v1.z + p1.w * v1.w;
                const float2 xr = *reinterpret_cast<const float2*>(xres + (size_t)m * N + n);
                float2 o;
                o.x = xr.x + acc[mt][nt][half * 2 + 0] + e0;
                o.y = xr.y + acc[mt][nt][half * 2 + 1] + e1;
                *reinterpret_cast<float2*>(outf + (size_t)m * N + n) = o;
            }
        }
    }
}

// ---------------------------------------------------------------------------
#define G1_SMEM (4 * STG32)   // 108544
#define G2_SMEM (4 * STG32)   // 108544

extern "C" void kernel_launch(void* const* d_in, const int* in_sizes, int n_in,
                              void* d_out, int out_size)
{
    const float* x    = (const float*)d_in[0];
    const float* ada  = (const float*)d_in[1];
    const float* base = (const float*)d_in[2];
    const float* w1   = (const float*)d_in[3];
    const float* b1   = (const float*)d_in[4];
    const float* w2   = (const float*)d_in[5];
    const float* b2   = (const float*)d_in[6];
    const float* ln_g = (const float*)d_in[7];
    const float* ln_b = (const float*)d_in[8];
    float* out = (float*)d_out;

    __half *ae, *h, *x16, *base16, *hpart16;
    float *xwpart, *Pp;
    cudaGetSymbolAddress((void**)&ae, g_ae);
    cudaGetSymbolAddress((void**)&h,  g_h);
    cudaGetSymbolAddress((void**)&x16, g_x16);
    cudaGetSymbolAddress((void**)&base16, g_base16);
    cudaGetSymbolAddress((void**)&hpart16, g_hpart16);
    cudaGetSymbolAddress((void**)&xwpart, g_xwpart);
    cudaGetSymbolAddress((void**)&Pp, g_Ppart);

    cudaFuncSetAttribute((const void*)pipe_gemm32_kernel<0, 4, 4, 3, 1, 8>,
                         cudaFuncAttributeMaxDynamicSharedMemorySize, G1_SMEM);
    cudaFuncSetAttribute((const void*)pipe_gemm32_kernel<2, 16, 4, 3, 2, 128>,
                         cudaFuncAttributeMaxDynamicSharedMemorySize, G2_SMEM);
    cudaFuncSetAttribute((const void*)gemm_final_kernel,
                         cudaFuncAttributeMaxDynamicSharedMemorySize, FSMEM);

    int n4x = NB * NT * ND / 4, n4tot = n4x + ND * ND / 4;

    // LN (G1's producer)
    ln_kernel<<<NB, 256>>>(ada, ln_g, ln_b, ae);

    // G1 + fused x/base cvt (blocks x>=8, z==0 do grid-stride cvt)
    pipe_gemm32_kernel<0, 4, 4, 3, 1, 8><<<dim3(148, 1, KSPLIT), 256, G1_SMEM>>>(
        ae, w1, NINTER, nullptr, hpart16,
        (const float4*)x, x16, n4x, (const float4*)base, base16, n4tot);
    reduce_gelu16_kernel<<<NB * NINTER / 2 / 256, 256>>>(
        (const __half2*)hpart16, b1, h);

    // G2: split-K x2, 4-stage pipeline, 2 CTAs/SM
    pipe_gemm32_kernel<2, 16, 4, 3, 2, 128><<<dim3(NW2 / 128, 1, 2), 256, G2_SMEM>>>(
        h, w2, NW2, xwpart, nullptr,
        nullptr, nullptr, 0, nullptr, nullptr, 0);

    // low-rank path + fused final GEMM
    p_mma_kernel<<<dim3(NB, PCHUNKS), 256>>>(x16, xwpart, b2, Pp);
    gemm_final_kernel<<<dim3(ND / 128, NB * NT / BM), 256, FSMEM>>>(
        x16, base16, out, x, Pp, xwpart, b2);
}

// round 15
// speedup vs baseline: 1.1327x; 1.1327x over previous
#include <cuda_runtime.h>
#include <cuda_fp16.h>
#include <cstdint>
#include <math.h>

#define NB     128
#define NT     32
#define ND     1024
#define NADA   1024
#define NINTER 1024
#define NRANK  8
#define GK     1024
#define BM     128
#define BK     32
#define SRA    80            // A row: 32 halves (64B) + 16B pad
#define ATILE  (128 * SRA)   // 10240
#define SRB32  528           // B fp32 row: 512B + 16B pad
#define B32TILE (32 * SRB32) // 16896
#define STG32  (ATILE + B32TILE)  // 27136
#define KSPLIT 8
#define NW2    (2 * ND * NRANK)   // 16384

// ---- P via tensor cores ----
#define PCHUNKS 4
#define PCD     256
#define PSZ     (NB * NT * NRANK)
#define XS_STRIDE 528
#define XA_PAD  12

// ---- final GEMM ----
#define FBK    64
#define FNIT   (GK / FBK)
#define FSRA   144
#define FSRB   272
#define FATILE (128 * FSRA)
#define FBTILE (64 * FSRB)
#define FSTAGE (FATILE + FBTILE)
#define FSMEM  (3 * FSTAGE)

// ---------------- scratch ----------------------------------------------------
__device__ __half g_ae[NB * NADA];
__device__ __half g_h[NB * NINTER];
__device__ __half g_x16[NB * NT * ND];
__device__ __half g_base16[ND * ND];
__device__ __half g_hpart16[KSPLIT * NB * NINTER];
__device__ __half g_xwpart16[2 * NB * NW2];   // G2 split-K fp16 partials
__device__ float  g_Ppart[PCHUNKS * PSZ];

// ---------------- PTX helpers -------------------------------------------------
__device__ __forceinline__ uint32_t smem_u32(const void* p) {
    uint32_t a;
    asm("{ .reg .u64 t; cvta.to.shared.u64 t, %1; cvt.u32.u64 %0, t; }" : "=r"(a) : "l"(p));
    return a;
}
#define CP16(sa, ga) \
    asm volatile("cp.async.cg.shared.global [%0], [%1], 16;" :: "r"(sa), "l"(ga))
#define CP_COMMIT() asm volatile("cp.async.commit_group;")
#define CP_WAIT(n)  asm volatile("cp.async.wait_group %0;" :: "n"(n))
#define LDSM4(r, addr) \
    asm volatile("ldmatrix.sync.aligned.m8n8.x4.shared.b16 {%0,%1,%2,%3}, [%4];" \
        : "=r"((r)[0]), "=r"((r)[1]), "=r"((r)[2]), "=r"((r)[3]) : "r"(addr))
#define LDSM4T(r, addr) \
    asm volatile("ldmatrix.sync.aligned.m8n8.x4.trans.shared.b16 {%0,%1,%2,%3}, [%4];" \
        : "=r"((r)[0]), "=r"((r)[1]), "=r"((r)[2]), "=r"((r)[3]) : "r"(addr))
#define MMA_F16(d, a, b0, b1) \
    asm volatile("mma.sync.aligned.m16n8k16.row.col.f32.f16.f16.f32 " \
        "{%0,%1,%2,%3},{%4,%5,%6,%7},{%8,%9},{%0,%1,%2,%3};" \
        : "+f"((d)[0]), "+f"((d)[1]), "+f"((d)[2]), "+f"((d)[3]) \
        : "r"((a)[0]), "r"((a)[1]), "r"((a)[2]), "r"((a)[3]), "r"(b0), "r"(b1))

__device__ __forceinline__ float gelu_exact(float v) {
    return 0.5f * v * (1.0f + erff(v * 0.70710678118654752f));
}

// ---------------- fused prep: fp32->fp16 (x, base) + layernorm ----------------
__global__ __launch_bounds__(256) void prep_kernel(
    const float4* __restrict__ srcx, __half* __restrict__ dstx, int n4x,
    const float4* __restrict__ srcb, __half* __restrict__ dstb, int n4tot, int ncvt,
    const float* __restrict__ ada, const float* __restrict__ gamma,
    const float* __restrict__ beta, __half* __restrict__ outh)
{
    if ((int)blockIdx.x < ncvt) {
        int i = blockIdx.x * 256 + threadIdx.x;
        if (i >= n4tot) return;
        const float4* s; __half* d; int j;
        if (i < n4x) { s = srcx; d = dstx; j = i; }
        else         { s = srcb; d = dstb; j = i - n4x; }
        float4 v = s[j];
        __half2 hh[2] = { __floats2half2_rn(v.x, v.y), __floats2half2_rn(v.z, v.w) };
        *reinterpret_cast<uint2*>(d + (size_t)j * 4) = *reinterpret_cast<uint2*>(hh);
        return;
    }
    int row = blockIdx.x - ncvt;
    const float4 v = reinterpret_cast<const float4*>(ada + (size_t)row * NADA)[threadIdx.x];
    float s  = v.x + v.y + v.z + v.w;
    float ss = v.x * v.x + v.y * v.y + v.z * v.z + v.w * v.w;
    __shared__ float rs[8], rq[8];
    #pragma unroll
    for (int o = 16; o > 0; o >>= 1) {
        s  += __shfl_xor_sync(0xFFFFFFFFu, s, o);
        ss += __shfl_xor_sync(0xFFFFFFFFu, ss, o);
    }
    int warp = threadIdx.x >> 5, lane = threadIdx.x & 31;
    if (lane == 0) { rs[warp] = s; rq[warp] = ss; }
    __syncthreads();
    float sum = 0.f, sumsq = 0.f;
    #pragma unroll
    for (int i = 0; i < 8; i++) { sum += rs[i]; sumsq += rq[i]; }
    const float inv_n = 1.0f / NADA;
    float mu = sum * inv_n;
    float rstd = rsqrtf(sumsq * inv_n - mu * mu + 1e-5f);
    const float4 gv = reinterpret_cast<const float4*>(gamma)[threadIdx.x];
    const float4 bv = reinterpret_cast<const float4*>(beta)[threadIdx.x];
    float o0 = (v.x - mu) * rstd * gv.x + bv.x;
    float o1 = (v.y - mu) * rstd * gv.y + bv.y;
    float o2 = (v.z - mu) * rstd * gv.z + bv.z;
    float o3 = (v.w - mu) * rstd * gv.w + bv.w;
    __half2 hh[2] = { __floats2half2_rn(o0, o1), __floats2half2_rn(o2, o3) };
    *reinterpret_cast<uint2*>(outh + (size_t)row * NADA + threadIdx.x * 4) =
        *reinterpret_cast<uint2*>(hh);
}

// ---------------- reduce fp16 split-K partials + bias + GELU -> fp16 ----------
__global__ __launch_bounds__(256) void reduce_gelu16_kernel(
    const __half2* __restrict__ part, const float* __restrict__ b1,
    __half* __restrict__ h)
{
    int i = blockIdx.x * 256 + threadIdx.x;
    float sx = 0.f, sy = 0.f;
    #pragma unroll
    for (int z = 0; z < KSPLIT; z++) {
        float2 f = __half22float2(part[(size_t)z * (NB * NINTER / 2) + i]);
        sx += f.x; sy += f.y;
    }
    const float2 bb = *reinterpret_cast<const float2*>(b1 + ((2 * i) & (NINTER - 1)));
    *reinterpret_cast<__half2*>(h + (size_t)i * 2) =
        __floats2half2_rn(gelu_exact(sx + bb.x), gelu_exact(sy + bb.y));
}

// ---------------- P via tensor cores (xa = part0 + part1 + b2) ----------------
__global__ __launch_bounds__(256) void p_mma_kernel(
    const __half* __restrict__ x16, const __half* __restrict__ xwpart,
    const float* __restrict__ b2, float* __restrict__ Pp)
{
    __shared__ __align__(16) char xs[NT * XS_STRIDE];
    __shared__ float xa[PCD * XA_PAD];
    int b = blockIdx.x, cch = blockIdx.y;
    int tid = threadIdx.x;

    #pragma unroll
    for (int i = 0; i < 4; i++) {
        int c = tid + i * 256;
        int t = c >> 5, seg = c & 31;
        *reinterpret_cast<uint4*>(xs + t * XS_STRIDE + seg * 16) =
            *reinterpret_cast<const uint4*>(x16 + ((size_t)b * NT + t) * ND + cch * PCD + seg * 8);
    }
    int obase = cch * PCD * NRANK;
    const __half2* p0 = reinterpret_cast<const __half2*>(xwpart + (size_t)b * NW2 + obase);
    const __half2* p1 = reinterpret_cast<const __half2*>(
        xwpart + (size_t)NB * NW2 + (size_t)b * NW2 + obase);
    #pragma unroll
    for (int i = 0; i < 4; i++) {
        int i2 = tid + i * 256;            // half2 index, 1024 total
        int d = (2 * i2) >> 3, r = (2 * i2) & 7;
        float2 a = __half22float2(p0[i2]);
        float2 c = __half22float2(p1[i2]);
        float2 bb = *reinterpret_cast<const float2*>(b2 + obase + 2 * i2);
        xa[d * XA_PAD + r]     = a.x + c.x + bb.x;
        xa[d * XA_PAD + r + 1] = a.y + c.y + bb.y;
    }
    __syncthreads();

    if (tid < 32) {
        int lane = tid;
        float acc[2][4];
        #pragma unroll
        for (int mt = 0; mt < 2; mt++)
            #pragma unroll
            for (int e = 0; e < 4; e++) acc[mt][e] = 0.f;

        uint32_t sxs = smem_u32(xs);
        const int a_row = lane & 15;
        const int a_off = (lane >> 4) * 16;
        const int b_n   = lane >> 2;
        const int b_kp  = (lane & 3) * 2;

        #pragma unroll
        for (int ks = 0; ks < PCD / 16; ks++) {
            uint32_t af[2][4];
            LDSM4(af[0], sxs + a_row * XS_STRIDE + ks * 32 + a_off);
            LDSM4(af[1], sxs + (16 + a_row) * XS_STRIDE + ks * 32 + a_off);
            int k0 = ks * 16 + b_kp;
            float f0 = xa[(k0 + 0) * XA_PAD + b_n];
            float f1 = xa[(k0 + 1) * XA_PAD + b_n];
            float f2 = xa[(k0 + 8) * XA_PAD + b_n];
            float f3 = xa[(k0 + 9) * XA_PAD + b_n];
            __half2 h01 = __floats2half2_rn(f0, f1);
            __half2 h23 = __floats2half2_rn(f2, f3);
            uint32_t b0 = *reinterpret_cast<uint32_t*>(&h01);
            uint32_t b1 = *reinterpret_cast<uint32_t*>(&h23);
            MMA_F16(acc[0], af[0], b0, b1);
            MMA_F16(acc[1], af[1], b0, b1);
        }

        float* pdst = Pp + (size_t)cch * PSZ + (size_t)b * NT * NRANK;
        #pragma unroll
        for (int mt = 0; mt < 2; mt++) {
            int row = mt * 16 + (lane >> 2);
            int col = (lane & 3) * 2;
            *reinterpret_cast<float2*>(pdst + row * NRANK + col) =
                make_float2(acc[mt][0], acc[mt][1]);
            *reinterpret_cast<float2*>(pdst + (row + 8) * NRANK + col) =
                make_float2(acc[mt][2], acc[mt][3]);
        }
    }
}

// ---------------- pipelined GEMM, A fp16 + B fp32 (cvt in fragment load) ------
// MODE 0 (G1): split-K fp16 partials. MODE 2 (G2): split-K fp16 partials.
// Output stride per z: NB * N halves.
template<int MODE, int NIT, int NSTGt, int LA, int MAXBLK>
__global__ __launch_bounds__(256, MAXBLK) void pipe_gemm32_kernel(
    const __half* __restrict__ A, const float* __restrict__ B, int N,
    __half* __restrict__ outh)
{
    extern __shared__ char smem[];
    const int tid = threadIdx.x, wid = tid >> 5, lane = tid & 31;
    const int m0 = blockIdx.y * BM, n0 = blockIdx.x * 128;
    const int kb = blockIdx.z * (NIT * BK);
    const int wm = wid & 1, wn = wid >> 1;
    const uint32_t sb = smem_u32(smem);

    float acc[4][4][4];
    #pragma unroll
    for (int i = 0; i < 4; i++)
        #pragma unroll
        for (int j = 0; j < 4; j++)
            #pragma unroll
            for (int e = 0; e < 4; e++) acc[i][j][e] = 0.f;

    auto issue = [&](int c) {
        uint32_t st = sb + (c % NSTGt) * STG32;
        int k0 = kb + c * BK;
        #pragma unroll
        for (int i = 0; i < 2; i++) {
            int ch = tid + i * 256, r = ch >> 2, cc = ch & 3;
            CP16(st + r * SRA + cc * 16, A + (size_t)(m0 + r) * GK + k0 + cc * 8);
        }
        #pragma unroll
        for (int i = 0; i < 4; i++) {
            int ch = tid + i * 256, r = ch >> 5, cc = ch & 31;
            CP16(st + ATILE + r * SRB32 + cc * 16, B + (size_t)(k0 + r) * N + n0 + cc * 4);
        }
        CP_COMMIT();
    };

    const int a_row = wm * 64 + (lane & 15);
    const int a_off = (lane >> 4) * 16;
    const int b_n   = lane >> 2;
    const int b_kp  = (lane & 3) * 2;

    #pragma unroll
    for (int s = 0; s < LA && s < NIT; s++) issue(s);

    for (int c = 0; c < NIT; c++) {
        int rem = NIT - 1 - c;
        int cap = rem < (LA - 1) ? rem : (LA - 1);
        if (cap >= 3) CP_WAIT(3);
        else if (cap == 2) CP_WAIT(2);
        else if (cap == 1) CP_WAIT(1);
        else CP_WAIT(0);
        __syncthreads();
        if (c + LA < NIT) issue(c + LA);

        const char* bstg = smem + ((c % NSTGt) * STG32) + ATILE;
        uint32_t abase = sb + (c % NSTGt) * STG32;
        #pragma unroll
        for (int ks = 0; ks < 2; ks++) {
            uint32_t af[4][4];
            #pragma unroll
            for (int mt = 0; mt < 4; mt++)
                LDSM4(af[mt], abase + (a_row + mt * 16) * SRA + ks * 32 + a_off);
            #pragma unroll
            for (int nt = 0; nt < 4; nt++) {
                int ncol = wn * 32 + nt * 8 + b_n;
                const char* col = bstg + (size_t)ncol * 4;
                int r0 = ks * 16 + b_kp;
                float f0 = *reinterpret_cast<const float*>(col + (r0 + 0) * SRB32);
                float f1 = *reinterpret_cast<const float*>(col + (r0 + 1) * SRB32);
                float f2 = *reinterpret_cast<const float*>(col + (r0 + 8) * SRB32);
                float f3 = *reinterpret_cast<const float*>(col + (r0 + 9) * SRB32);
                __half2 h01 = __floats2half2_rn(f0, f1);
                __half2 h23 = __floats2half2_rn(f2, f3);
                uint32_t b0 = *reinterpret_cast<uint32_t*>(&h01);
                uint32_t b1 = *reinterpret_cast<uint32_t*>(&h23);
                #pragma unroll
                for (int mt = 0; mt < 4; mt++)
                    MMA_F16(acc[mt][nt], af[mt], b0, b1);
            }
        }
    }

    __half* po = outh + (size_t)blockIdx.z * ((size_t)NB * N);
    #pragma unroll
    for (int mt = 0; mt < 4; mt++) {
        int r_in0 = wm * 64 + mt * 16 + (lane >> 2);
        #pragma unroll
        for (int half = 0; half < 2; half++) {
            int m = m0 + r_in0 + half * 8;
            #pragma unroll
            for (int nt = 0; nt < 4; nt++) {
                int n = n0 + wn * 32 + nt * 8 + (lane & 3) * 2;
                *reinterpret_cast<__half2*>(po + (size_t)m * N + n) =
                    __floats2half2_rn(acc[mt][nt][half * 2 + 0],
                                      acc[mt][nt][half * 2 + 1]);
            }
        }
    }
}

// ---------------- final GEMM: cp.async 3-stage, BK=64, fp16 x fp16 ------------
__global__ __launch_bounds__(256, 2) void gemm_final_kernel(
    const __half* __restrict__ A, const __half* __restrict__ B,
    float* __restrict__ outf, const float* __restrict__ xres,
    const float* __restrict__ Pp, const __half* __restrict__ xwpart,
    const float* __restrict__ b2)
{
    extern __shared__ char smem[];
    const int tid = threadIdx.x, wid = tid >> 5, lane = tid & 31;
    const int m0 = blockIdx.y * BM, n0 = blockIdx.x * 128;
    const int wm = wid & 1, wn = wid >> 1;
    const uint32_t sb = smem_u32(smem);
    const int N = ND;

    float acc[4][4][4];
    #pragma unroll
    for (int i = 0; i < 4; i++)
        #pragma unroll
        for (int j = 0; j < 4; j++)
            #pragma unroll
            for (int e = 0; e < 4; e++) acc[i][j][e] = 0.f;

    auto issue = [&](int c) {
        uint32_t st = sb + (c % 3) * FSTAGE;
        int k0 = c * FBK;
        #pragma unroll
        for (int i = 0; i < 4; i++) {
            int ch = tid + i * 256, r = ch >> 3, cc = ch & 7;
            CP16(st + r * FSRA + cc * 16, A + (size_t)(m0 + r) * GK + k0 + cc * 8);
        }
        #pragma unroll
        for (int i = 0; i < 4; i++) {
            int ch = tid + i * 256, r = ch >> 4, cc = ch & 15;
            CP16(st + FATILE + r * FSRB + cc * 16, B + (size_t)(k0 + r) * N + n0 + cc * 8);
        }
        CP_COMMIT();
    };

    const int a_row  = wm * 64 + (lane & 15);
    const int a_off  = (lane >> 4) * 16;
    const int b_row  = lane & 15;
    const int b_colb = wn * 64 + (lane >> 4) * 16;

    issue(0);
    issue(1);

    for (int c = 0; c < FNIT; c++) {
        if (c < FNIT - 1) CP_WAIT(1); else CP_WAIT(0);
        __syncthreads();
        if (c + 2 < FNIT) issue(c + 2);

        uint32_t base = sb + (c % 3) * FSTAGE;
        #pragma unroll
        for (int ks = 0; ks < 4; ks++) {
            uint32_t af[4][4];
            #pragma unroll
            for (int mt = 0; mt < 4; mt++)
                LDSM4(af[mt], base + (a_row + mt * 16) * FSRA + ks * 32 + a_off);
            uint32_t bf[4][2];
            #pragma unroll
            for (int pr = 0; pr < 2; pr++) {
                uint32_t r[4];
                LDSM4T(r, base + FATILE + (ks * 16 + b_row) * FSRB + b_colb + pr * 32);
                bf[pr * 2 + 0][0] = r[0]; bf[pr * 2 + 0][1] = r[1];
                bf[pr * 2 + 1][0] = r[2]; bf[pr * 2 + 1][1] = r[3];
            }
            #pragma unroll
            for (int mt = 0; mt < 4; mt++)
                #pragma unroll
                for (int nt = 0; nt < 4; nt++)
                    MMA_F16(acc[mt][nt], af[mt], bf[nt][0], bf[nt][1]);
        }
    }
    __syncthreads();

    // epilogue: + xres + P @ x_b^T  (x_b = part0 + part1 + b2)
    float* Ps  = reinterpret_cast<float*>(smem);
    float* xbs = reinterpret_cast<float*>(smem + 4096);
    for (int i = tid; i < BM * NRANK; i += 256) {
        float sv = 0.f;
        #pragma unroll
        for (int c = 0; c < PCHUNKS; c++)
            sv += Pp[(size_t)c * PSZ + (size_t)m0 * NRANK + i];
        Ps[i] = sv;
    }
    for (int i = tid; i < 4 * 128 * NRANK; i += 256) {
        int g = i >> 10, j = (i >> 3) & 127, r = i & 7;
        int bg = (m0 >> 5) + g;
        int o = ND * NRANK + (n0 + j) * NRANK + r;
        size_t go = (size_t)bg * NW2 + o;
        xbs[i] = __half2float(xwpart[go])
               + __half2float(xwpart[(size_t)NB * NW2 + go]) + b2[o];
    }
    __syncthreads();

    #pragma unroll
    for (int mt = 0; mt < 4; mt++) {
        int r_in0 = wm * 64 + mt * 16 + (lane >> 2);
        #pragma unroll
        for (int half = 0; half < 2; half++) {
            int r_in = r_in0 + half * 8;
            int m = m0 + r_in;
            int g = r_in >> 5;
            const float4* pr = reinterpret_cast<const float4*>(Ps + r_in * 8);
            float4 p0 = pr[0], p1 = pr[1];
            #pragma unroll
            for (int nt = 0; nt < 4; nt++) {
                int c_in = wn * 32 + nt * 8 + (lane & 3) * 2;
                int n = n0 + c_in;
                const float4* xb0 = reinterpret_cast<const float4*>(xbs + (g * 128 + c_in) * 8);
                const float4* xb1 = reinterpret_cast<const float4*>(xbs + (g * 128 + c_in + 1) * 8);
                float4 u0 = xb0[0], u1 = xb0[1], v0 = xb1[0], v1 = xb1[1];
                float e0 = p0.x * u0.x + p0.y * u0.y + p0.z * u0.z + p0.w * u0.w
                         + p1.x * u1.x + p1.y * u1.y + p1.z * u1.z + p1.w * u1.w;
                float e1 = p0.x * v0.x + p0.y * v0.y + p0.z * v0.z + p0.w * v0.w
                         + p1.x * v1.x + p1.y * v1.y + p1.z * v1.z + p1.w * v1.w;
                const float2 xr = *reinterpret_cast<const float2*>(xres + (size_t)m * N + n);
                float2 o;
                o.x = xr.x + acc[mt][nt][half * 2 + 0] + e0;
                o.y = xr.y + acc[mt][nt][half * 2 + 1] + e1;
                *reinterpret_cast<float2*>(outf + (size_t)m * N + n) = o;
            }
        }
    }
}

// ---------------------------------------------------------------------------
#define G1_SMEM (4 * STG32)   // 108544
#define G2_SMEM (3 * STG32)   // 81408

extern "C" void kernel_launch(void* const* d_in, const int* in_sizes, int n_in,
                              void* d_out, int out_size)
{
    const float* x    = (const float*)d_in[0];
    const float* ada  = (const float*)d_in[1];
    const float* base = (const float*)d_in[2];
    const float* w1   = (const float*)d_in[3];
    const float* b1   = (const float*)d_in[4];
    const float* w2   = (const float*)d_in[5];
    const float* b2   = (const float*)d_in[6];
    const float* ln_g = (const float*)d_in[7];
    const float* ln_b = (const float*)d_in[8];
    float* out = (float*)d_out;

    __half *ae, *h, *x16, *base16, *hpart16, *xwpart16;
    float *Pp;
    cudaGetSymbolAddress((void**)&ae, g_ae);
    cudaGetSymbolAddress((void**)&h,  g_h);
    cudaGetSymbolAddress((void**)&x16, g_x16);
    cudaGetSymbolAddress((void**)&base16, g_base16);
    cudaGetSymbolAddress((void**)&hpart16, g_hpart16);
    cudaGetSymbolAddress((void**)&xwpart16, g_xwpart16);
    cudaGetSymbolAddress((void**)&Pp, g_Ppart);

    cudaFuncSetAttribute((const void*)pipe_gemm32_kernel<0, 4, 4, 3, 1>,
                         cudaFuncAttributeMaxDynamicSharedMemorySize, G1_SMEM);
    cudaFuncSetAttribute((const void*)pipe_gemm32_kernel<2, 16, 3, 2, 2>,
                         cudaFuncAttributeMaxDynamicSharedMemorySize, G2_SMEM);
    cudaFuncSetAttribute((const void*)gemm_final_kernel,
                         cudaFuncAttributeMaxDynamicSharedMemorySize, FSMEM);

    // fused prep: cvt(x, base) + layernorm
    int n4x = NB * NT * ND / 4, n4b = ND * ND / 4;
    int ncvt = (n4x + n4b + 255) / 256;
    prep_kernel<<<ncvt + NB, 256>>>(
        (const float4*)x, x16, n4x, (const float4*)base, base16, n4x + n4b, ncvt,
        ada, ln_g, ln_b, ae);

    // hypernetwork
    pipe_gemm32_kernel<0, 4, 4, 3, 1><<<dim3(NINTER / 128, 1, KSPLIT), 256, G1_SMEM>>>(
        ae, w1, NINTER, hpart16);
    reduce_gelu16_kernel<<<NB * NINTER / 2 / 256, 256>>>(
        (const __half2*)hpart16, b1, h);

    // G2: split-K x2, fp16 partials
    pipe_gemm32_kernel<2, 16, 3, 2, 2><<<dim3(NW2 / 128, 1, 2), 256, G2_SMEM>>>(
        h, w2, NW2, xwpart16);

    // low-rank path + fused final GEMM
    p_mma_kernel<<<dim3(NB, PCHUNKS), 256>>>(x16, xwpart16, b2, Pp);
    gemm_final_kernel<<<dim3(ND / 128, NB * NT / BM), 256, FSMEM>>>(
        x16, base16, out, x, Pp, xwpart16, b2);
}

// round 16
// speedup vs baseline: 1.1533x; 1.0182x over previous
#include <cuda_runtime.h>
#include <cuda_fp16.h>
#include <cstdint>
#include <math.h>

#define NB     128
#define NT     32
#define ND     1024
#define NADA   1024
#define NINTER 1024
#define NRANK  8
#define GK     1024
#define BM     128
#define BK     32
#define SRA    80            // A row: 32 halves (64B) + 16B pad
#define ATILE  (128 * SRA)   // 10240
#define SRB32  528           // B fp32 row: 512B + 16B pad
#define B32TILE (32 * SRB32) // 16896
#define STG32  (ATILE + B32TILE)  // 27136
#define KSPLIT 8
#define NW2    (2 * ND * NRANK)   // 16384

// ---- P via tensor cores ----
#define PCHUNKS 4
#define PCD     256
#define PSZ     (NB * NT * NRANK)
#define XS_STRIDE 528
#define XA_PAD  12

// ---- final GEMM ----
#define FBK    64
#define FNIT   (GK / FBK)
#define FSRA   144
#define FSRB   272
#define FATILE (128 * FSRA)
#define FBTILE (64 * FSRB)
#define FSTAGE (FATILE + FBTILE)
#define FSMEM  (3 * FSTAGE)       // 107520 (>= 3*STG32 for G2 path)

// ---------------- scratch ----------------------------------------------------
__device__ __half g_ae[NB * NADA];
__device__ __half g_h[NB * NINTER];
__device__ __half g_x16[NB * NT * ND];
__device__ __half g_base16[ND * ND];
__device__ __half g_hpart16[KSPLIT * NB * NINTER];
__device__ __half g_xwpart16[2 * NB * NW2];
__device__ float  g_Ppart[PCHUNKS * PSZ];

// ---------------- PTX helpers -------------------------------------------------
__device__ __forceinline__ uint32_t smem_u32(const void* p) {
    uint32_t a;
    asm("{ .reg .u64 t; cvta.to.shared.u64 t, %1; cvt.u32.u64 %0, t; }" : "=r"(a) : "l"(p));
    return a;
}
#define CP16(sa, ga) \
    asm volatile("cp.async.cg.shared.global [%0], [%1], 16;" :: "r"(sa), "l"(ga))
#define CP_COMMIT() asm volatile("cp.async.commit_group;")
#define CP_WAIT(n)  asm volatile("cp.async.wait_group %0;" :: "n"(n))
#define LDSM4(r, addr) \
    asm volatile("ldmatrix.sync.aligned.m8n8.x4.shared.b16 {%0,%1,%2,%3}, [%4];" \
        : "=r"((r)[0]), "=r"((r)[1]), "=r"((r)[2]), "=r"((r)[3]) : "r"(addr))
#define LDSM4T(r, addr) \
    asm volatile("ldmatrix.sync.aligned.m8n8.x4.trans.shared.b16 {%0,%1,%2,%3}, [%4];" \
        : "=r"((r)[0]), "=r"((r)[1]), "=r"((r)[2]), "=r"((r)[3]) : "r"(addr))
#define MMA_F16(d, a, b0, b1) \
    asm volatile("mma.sync.aligned.m16n8k16.row.col.f32.f16.f16.f32 " \
        "{%0,%1,%2,%3},{%4,%5,%6,%7},{%8,%9},{%0,%1,%2,%3};" \
        : "+f"((d)[0]), "+f"((d)[1]), "+f"((d)[2]), "+f"((d)[3]) \
        : "r"((a)[0]), "r"((a)[1]), "r"((a)[2]), "r"((a)[3]), "r"(b0), "r"(b1))

__device__ __forceinline__ float gelu_exact(float v) {
    return 0.5f * v * (1.0f + erff(v * 0.70710678118654752f));
}

// ---------------- fused prep: fp32->fp16 (x, base) + layernorm ----------------
__global__ __launch_bounds__(256) void prep_kernel(
    const float4* __restrict__ srcx, __half* __restrict__ dstx, int n4x,
    const float4* __restrict__ srcb, __half* __restrict__ dstb, int n4tot, int ncvt,
    const float* __restrict__ ada, const float* __restrict__ gamma,
    const float* __restrict__ beta, __half* __restrict__ outh)
{
    if ((int)blockIdx.x < ncvt) {
        int i = blockIdx.x * 256 + threadIdx.x;
        if (i >= n4tot) return;
        const float4* s; __half* d; int j;
        if (i < n4x) { s = srcx; d = dstx; j = i; }
        else         { s = srcb; d = dstb; j = i - n4x; }
        float4 v = s[j];
        __half2 hh[2] = { __floats2half2_rn(v.x, v.y), __floats2half2_rn(v.z, v.w) };
        *reinterpret_cast<uint2*>(d + (size_t)j * 4) = *reinterpret_cast<uint2*>(hh);
        return;
    }
    int row = blockIdx.x - ncvt;
    const float4 v = reinterpret_cast<const float4*>(ada + (size_t)row * NADA)[threadIdx.x];
    float s  = v.x + v.y + v.z + v.w;
    float ss = v.x * v.x + v.y * v.y + v.z * v.z + v.w * v.w;
    __shared__ float rs[8], rq[8];
    #pragma unroll
    for (int o = 16; o > 0; o >>= 1) {
        s  += __shfl_xor_sync(0xFFFFFFFFu, s, o);
        ss += __shfl_xor_sync(0xFFFFFFFFu, ss, o);
    }
    int warp = threadIdx.x >> 5, lane = threadIdx.x & 31;
    if (lane == 0) { rs[warp] = s; rq[warp] = ss; }
    __syncthreads();
    float sum = 0.f, sumsq = 0.f;
    #pragma unroll
    for (int i = 0; i < 8; i++) { sum += rs[i]; sumsq += rq[i]; }
    const float inv_n = 1.0f / NADA;
    float mu = sum * inv_n;
    float rstd = rsqrtf(sumsq * inv_n - mu * mu + 1e-5f);
    const float4 gv = reinterpret_cast<const float4*>(gamma)[threadIdx.x];
    const float4 bv = reinterpret_cast<const float4*>(beta)[threadIdx.x];
    float o0 = (v.x - mu) * rstd * gv.x + bv.x;
    float o1 = (v.y - mu) * rstd * gv.y + bv.y;
    float o2 = (v.z - mu) * rstd * gv.z + bv.z;
    float o3 = (v.w - mu) * rstd * gv.w + bv.w;
    __half2 hh[2] = { __floats2half2_rn(o0, o1), __floats2half2_rn(o2, o3) };
    *reinterpret_cast<uint2*>(outh + (size_t)row * NADA + threadIdx.x * 4) =
        *reinterpret_cast<uint2*>(hh);
}

// ---------------- reduce fp16 split-K partials + bias + GELU -> fp16 ----------
__global__ __launch_bounds__(256) void reduce_gelu16_kernel(
    const __half2* __restrict__ part, const float* __restrict__ b1,
    __half* __restrict__ h)
{
    int i = blockIdx.x * 256 + threadIdx.x;
    float sx = 0.f, sy = 0.f;
    #pragma unroll
    for (int z = 0; z < KSPLIT; z++) {
        float2 f = __half22float2(part[(size_t)z * (NB * NINTER / 2) + i]);
        sx += f.x; sy += f.y;
    }
    const float2 bb = *reinterpret_cast<const float2*>(b1 + ((2 * i) & (NINTER - 1)));
    *reinterpret_cast<__half2*>(h + (size_t)i * 2) =
        __floats2half2_rn(gelu_exact(sx + bb.x), gelu_exact(sy + bb.y));
}

// ---------------- G1: pipelined GEMM, split-K fp16 partials -------------------
__global__ __launch_bounds__(256) void g1_kernel(
    const __half* __restrict__ A, const float* __restrict__ B,
    __half* __restrict__ outh)
{
    constexpr int NIT = 4, NSTGt = 4, LA = 3;
    const int N = NINTER;
    extern __shared__ char smem[];
    const int tid = threadIdx.x, wid = tid >> 5, lane = tid & 31;
    const int m0 = 0, n0 = blockIdx.x * 128;
    const int kb = blockIdx.z * (NIT * BK);
    const int wm = wid & 1, wn = wid >> 1;
    const uint32_t sb = smem_u32(smem);

    float acc[4][4][4];
    #pragma unroll
    for (int i = 0; i < 4; i++)
        #pragma unroll
        for (int j = 0; j < 4; j++)
            #pragma unroll
            for (int e = 0; e < 4; e++) acc[i][j][e] = 0.f;

    auto issue = [&](int c) {
        uint32_t st = sb + (c % NSTGt) * STG32;
        int k0 = kb + c * BK;
        #pragma unroll
        for (int i = 0; i < 2; i++) {
            int ch = tid + i * 256, r = ch >> 2, cc = ch & 3;
            CP16(st + r * SRA + cc * 16, A + (size_t)(m0 + r) * GK + k0 + cc * 8);
        }
        #pragma unroll
        for (int i = 0; i < 4; i++) {
            int ch = tid + i * 256, r = ch >> 5, cc = ch & 31;
            CP16(st + ATILE + r * SRB32 + cc * 16, B + (size_t)(k0 + r) * N + n0 + cc * 4);
        }
        CP_COMMIT();
    };

    const int a_row = wm * 64 + (lane & 15);
    const int a_off = (lane >> 4) * 16;
    const int b_n   = lane >> 2;
    const int b_kp  = (lane & 3) * 2;

    #pragma unroll
    for (int s = 0; s < LA && s < NIT; s++) issue(s);

    for (int c = 0; c < NIT; c++) {
        int rem = NIT - 1 - c;
        int cap = rem < (LA - 1) ? rem : (LA - 1);
        if (cap >= 2) CP_WAIT(2);
        else if (cap == 1) CP_WAIT(1);
        else CP_WAIT(0);
        __syncthreads();
        if (c + LA < NIT) issue(c + LA);

        const char* bstg = smem + ((c % NSTGt) * STG32) + ATILE;
        uint32_t abase = sb + (c % NSTGt) * STG32;
        #pragma unroll
        for (int ks = 0; ks < 2; ks++) {
            uint32_t af[4][4];
            #pragma unroll
            for (int mt = 0; mt < 4; mt++)
                LDSM4(af[mt], abase + (a_row + mt * 16) * SRA + ks * 32 + a_off);
            #pragma unroll
            for (int nt = 0; nt < 4; nt++) {
                int ncol = wn * 32 + nt * 8 + b_n;
                const char* col = bstg + (size_t)ncol * 4;
                int r0 = ks * 16 + b_kp;
                float f0 = *reinterpret_cast<const float*>(col + (r0 + 0) * SRB32);
                float f1 = *reinterpret_cast<const float*>(col + (r0 + 1) * SRB32);
                float f2 = *reinterpret_cast<const float*>(col + (r0 + 8) * SRB32);
                float f3 = *reinterpret_cast<const float*>(col + (r0 + 9) * SRB32);
                __half2 h01 = __floats2half2_rn(f0, f1);
                __half2 h23 = __floats2half2_rn(f2, f3);
                uint32_t b0 = *reinterpret_cast<uint32_t*>(&h01);
                uint32_t b1 = *reinterpret_cast<uint32_t*>(&h23);
                #pragma unroll
                for (int mt = 0; mt < 4; mt++)
                    MMA_F16(acc[mt][nt], af[mt], b0, b1);
            }
        }
    }

    __half* po = outh + (size_t)blockIdx.z * ((size_t)NB * N);
    #pragma unroll
    for (int mt = 0; mt < 4; mt++) {
        int r_in0 = wm * 64 + mt * 16 + (lane >> 2);
        #pragma unroll
        for (int half = 0; half < 2; half++) {
            int m = m0 + r_in0 + half * 8;
            #pragma unroll
            for (int nt = 0; nt < 4; nt++) {
                int n = n0 + wn * 32 + nt * 8 + (lane & 3) * 2;
                *reinterpret_cast<__half2*>(po + (size_t)m * N + n) =
                    __floats2half2_rn(acc[mt][nt][half * 2 + 0],
                                      acc[mt][nt][half * 2 + 1]);
            }
        }
    }
}

// ---------------- FUSED: G2 (odd blocks) + final mainloop (even blocks) -------
__global__ __launch_bounds__(256, 2) void fused_kernel(
    const __half* __restrict__ h, const float* __restrict__ w2,
    __half* __restrict__ xwpart,
    const __half* __restrict__ x16, const __half* __restrict__ base16,
    float* __restrict__ outf, const float* __restrict__ xres)
{
    extern __shared__ char smem[];
    const int tid = threadIdx.x, wid = tid >> 5, lane = tid & 31;
    const int wm = wid & 1, wn = wid >> 1;
    const uint32_t sb = smem_u32(smem);
    const int id = blockIdx.x >> 1;

    if (blockIdx.x & 1) {
        // ---- G2 path: K-split x2, NSTG=3, LA=2, fp16 partials ----
        constexpr int NIT = 16, NSTGt = 3, LA = 2;
        const int N = NW2;
        const int n0 = (id & 127) * 128;
        const int z  = id >> 7;
        const int kb = z * (NIT * BK);

        float acc[4][4][4];
        #pragma unroll
        for (int i = 0; i < 4; i++)
            #pragma unroll
            for (int j = 0; j < 4; j++)
                #pragma unroll
                for (int e = 0; e < 4; e++) acc[i][j][e] = 0.f;

        auto issue = [&](int c) {
            uint32_t st = sb + (c % NSTGt) * STG32;
            int k0 = kb + c * BK;
            #pragma unroll
            for (int i = 0; i < 2; i++) {
                int ch = tid + i * 256, r = ch >> 2, cc = ch & 3;
                CP16(st + r * SRA + cc * 16, h + (size_t)r * GK + k0 + cc * 8);
            }
            #pragma unroll
            for (int i = 0; i < 4; i++) {
                int ch = tid + i * 256, r = ch >> 5, cc = ch & 31;
                CP16(st + ATILE + r * SRB32 + cc * 16, w2 + (size_t)(k0 + r) * N + n0 + cc * 4);
            }
            CP_COMMIT();
        };

        const int a_row = wm * 64 + (lane & 15);
        const int a_off = (lane >> 4) * 16;
        const int b_n   = lane >> 2;
        const int b_kp  = (lane & 3) * 2;

        issue(0); issue(1);

        for (int c = 0; c < NIT; c++) {
            if (c < NIT - 1) CP_WAIT(1); else CP_WAIT(0);
            __syncthreads();
            if (c + LA < NIT) issue(c + LA);

            const char* bstg = smem + ((c % NSTGt) * STG32) + ATILE;
            uint32_t abase = sb + (c % NSTGt) * STG32;
            #pragma unroll
            for (int ks = 0; ks < 2; ks++) {
                uint32_t af[4][4];
                #pragma unroll
                for (int mt = 0; mt < 4; mt++)
                    LDSM4(af[mt], abase + (a_row + mt * 16) * SRA + ks * 32 + a_off);
                #pragma unroll
                for (int nt = 0; nt < 4; nt++) {
                    int ncol = wn * 32 + nt * 8 + b_n;
                    const char* col = bstg + (size_t)ncol * 4;
                    int r0 = ks * 16 + b_kp;
                    float f0 = *reinterpret_cast<const float*>(col + (r0 + 0) * SRB32);
                    float f1 = *reinterpret_cast<const float*>(col + (r0 + 1) * SRB32);
                    float f2 = *reinterpret_cast<const float*>(col + (r0 + 8) * SRB32);
                    float f3 = *reinterpret_cast<const float*>(col + (r0 + 9) * SRB32);
                    __half2 h01 = __floats2half2_rn(f0, f1);
                    __half2 h23 = __floats2half2_rn(f2, f3);
                    uint32_t b0 = *reinterpret_cast<uint32_t*>(&h01);
                    uint32_t b1 = *reinterpret_cast<uint32_t*>(&h23);
                    #pragma unroll
                    for (int mt = 0; mt < 4; mt++)
                        MMA_F16(acc[mt][nt], af[mt], b0, b1);
                }
            }
        }

        __half* po = xwpart + (size_t)z * ((size_t)NB * N);
        #pragma unroll
        for (int mt = 0; mt < 4; mt++) {
            int r_in0 = wm * 64 + mt * 16 + (lane >> 2);
            #pragma unroll
            for (int half = 0; half < 2; half++) {
                int m = r_in0 + half * 8;
                #pragma unroll
                for (int nt = 0; nt < 4; nt++) {
                    int n = n0 + wn * 32 + nt * 8 + (lane & 3) * 2;
                    *reinterpret_cast<__half2*>(po + (size_t)m * N + n) =
                        __floats2half2_rn(acc[mt][nt][half * 2 + 0],
                                          acc[mt][nt][half * 2 + 1]);
                }
            }
        }
    } else {
        // ---- final mainloop path: out = xres + x16 @ base16 ----
        const int N = ND;
        const int n0 = (id & 7) * 128;
        const int m0 = (id >> 3) * BM;

        float acc[4][4][4];
        #pragma unroll
        for (int i = 0; i < 4; i++)
            #pragma unroll
            for (int j = 0; j < 4; j++)
                #pragma unroll
                for (int e = 0; e < 4; e++) acc[i][j][e] = 0.f;

        auto issue = [&](int c) {
            uint32_t st = sb + (c % 3) * FSTAGE;
            int k0 = c * FBK;
            #pragma unroll
            for (int i = 0; i < 4; i++) {
                int ch = tid + i * 256, r = ch >> 3, cc = ch & 7;
                CP16(st + r * FSRA + cc * 16, x16 + (size_t)(m0 + r) * GK + k0 + cc * 8);
            }
            #pragma unroll
            for (int i = 0; i < 4; i++) {
                int ch = tid + i * 256, r = ch >> 4, cc = ch & 15;
                CP16(st + FATILE + r * FSRB + cc * 16, base16 + (size_t)(k0 + r) * N + n0 + cc * 8);
            }
            CP_COMMIT();
        };

        const int a_row  = wm * 64 + (lane & 15);
        const int a_off  = (lane >> 4) * 16;
        const int b_row  = lane & 15;
        const int b_colb = wn * 64 + (lane >> 4) * 16;

        issue(0); issue(1);

        for (int c = 0; c < FNIT; c++) {
            if (c < FNIT - 1) CP_WAIT(1); else CP_WAIT(0);
            __syncthreads();
            if (c + 2 < FNIT) issue(c + 2);

            uint32_t base = sb + (c % 3) * FSTAGE;
            #pragma unroll
            for (int ks = 0; ks < 4; ks++) {
                uint32_t af[4][4];
                #pragma unroll
                for (int mt = 0; mt < 4; mt++)
                    LDSM4(af[mt], base + (a_row + mt * 16) * FSRA + ks * 32 + a_off);
                uint32_t bf[4][2];
                #pragma unroll
                for (int pr = 0; pr < 2; pr++) {
                    uint32_t r[4];
                    LDSM4T(r, base + FATILE + (ks * 16 + b_row) * FSRB + b_colb + pr * 32);
                    bf[pr * 2 + 0][0] = r[0]; bf[pr * 2 + 0][1] = r[1];
                    bf[pr * 2 + 1][0] = r[2]; bf[pr * 2 + 1][1] = r[3];
                }
                #pragma unroll
                for (int mt = 0; mt < 4; mt++)
                    #pragma unroll
                    for (int nt = 0; nt < 4; nt++)
                        MMA_F16(acc[mt][nt], af[mt], bf[nt][0], bf[nt][1]);
            }
        }

        #pragma unroll
        for (int mt = 0; mt < 4; mt++) {
            int r_in0 = wm * 64 + mt * 16 + (lane >> 2);
            #pragma unroll
            for (int half = 0; half < 2; half++) {
                int m = m0 + r_in0 + half * 8;
                #pragma unroll
                for (int nt = 0; nt < 4; nt++) {
                    int n = n0 + wn * 32 + nt * 8 + (lane & 3) * 2;
                    const float2 xr = *reinterpret_cast<const float2*>(xres + (size_t)m * N + n);
                    float2 o;
                    o.x = xr.x + acc[mt][nt][half * 2 + 0];
                    o.y = xr.y + acc[mt][nt][half * 2 + 1];
                    *reinterpret_cast<float2*>(outf + (size_t)m * N + n) = o;
                }
            }
        }
    }
}

// ---------------- P via tensor cores (xa = part0 + part1 + b2) ----------------
__global__ __launch_bounds__(256) void p_mma_kernel(
    const __half* __restrict__ x16, const __half* __restrict__ xwpart,
    const float* __restrict__ b2, float* __restrict__ Pp)
{
    __shared__ __align__(16) char xs[NT * XS_STRIDE];
    __shared__ float xa[PCD * XA_PAD];
    int b = blockIdx.x, cch = blockIdx.y;
    int tid = threadIdx.x;

    #pragma unroll
    for (int i = 0; i < 4; i++) {
        int c = tid + i * 256;
        int t = c >> 5, seg = c & 31;
        *reinterpret_cast<uint4*>(xs + t * XS_STRIDE + seg * 16) =
            *reinterpret_cast<const uint4*>(x16 + ((size_t)b * NT + t) * ND + cch * PCD + seg * 8);
    }
    int obase = cch * PCD * NRANK;
    const __half2* p0 = reinterpret_cast<const __half2*>(xwpart + (size_t)b * NW2 + obase);
    const __half2* p1 = reinterpret_cast<const __half2*>(
        xwpart + (size_t)NB * NW2 + (size_t)b * NW2 + obase);
    #pragma unroll
    for (int i = 0; i < 4; i++) {
        int i2 = tid + i * 256;
        int d = (2 * i2) >> 3, r = (2 * i2) & 7;
        float2 a = __half22float2(p0[i2]);
        float2 c = __half22float2(p1[i2]);
        float2 bb = *reinterpret_cast<const float2*>(b2 + obase + 2 * i2);
        xa[d * XA_PAD + r]     = a.x + c.x + bb.x;
        xa[d * XA_PAD + r + 1] = a.y + c.y + bb.y;
    }
    __syncthreads();

    if (tid < 32) {
        int lane = tid;
        float acc[2][4];
        #pragma unroll
        for (int mt = 0; mt < 2; mt++)
            #pragma unroll
            for (int e = 0; e < 4; e++) acc[mt][e] = 0.f;

        uint32_t sxs = smem_u32(xs);
        const int a_row = lane & 15;
        const int a_off = (lane >> 4) * 16;
        const int b_n   = lane >> 2;
        const int b_kp  = (lane & 3) * 2;

        #pragma unroll
        for (int ks = 0; ks < PCD / 16; ks++) {
            uint32_t af[2][4];
            LDSM4(af[0], sxs + a_row * XS_STRIDE + ks * 32 + a_off);
            LDSM4(af[1], sxs + (16 + a_row) * XS_STRIDE + ks * 32 + a_off);
            int k0 = ks * 16 + b_kp;
            float f0 = xa[(k0 + 0) * XA_PAD + b_n];
            float f1 = xa[(k0 + 1) * XA_PAD + b_n];
            float f2 = xa[(k0 + 8) * XA_PAD + b_n];
            float f3 = xa[(k0 + 9) * XA_PAD + b_n];
            __half2 h01 = __floats2half2_rn(f0, f1);
            __half2 h23 = __floats2half2_rn(f2, f3);
            uint32_t b0 = *reinterpret_cast<uint32_t*>(&h01);
            uint32_t b1 = *reinterpret_cast<uint32_t*>(&h23);
            MMA_F16(acc[0], af[0], b0, b1);
            MMA_F16(acc[1], af[1], b0, b1);
        }

        float* pdst = Pp + (size_t)cch * PSZ + (size_t)b * NT * NRANK;
        #pragma unroll
        for (int mt = 0; mt < 2; mt++) {
            int row = mt * 16 + (lane >> 2);
            int col = (lane & 3) * 2;
            *reinterpret_cast<float2*>(pdst + row * NRANK + col) =
                make_float2(acc[mt][0], acc[mt][1]);
            *reinterpret_cast<float2*>(pdst + (row + 8) * NRANK + col) =
                make_float2(acc[mt][2], acc[mt][3]);
        }
    }
}

// ---------------- deferred LoRA: out += P @ x_b^T ------------------------------
#define XBP 516
__global__ __launch_bounds__(256) void lora_add_kernel(
    float* __restrict__ out, const float* __restrict__ Pp,
    const __half* __restrict__ xwpart, const float* __restrict__ b2)
{
    __shared__ float Ps[BM * NRANK];       // 4 KB
    __shared__ float xbs[NRANK * XBP];     // 16.5 KB, [r][g*128+j]
    const int tid = threadIdx.x;
    const int n0 = blockIdx.x * 128, m0 = blockIdx.y * BM;

    for (int i = tid; i < BM * NRANK; i += 256) {
        float sv = 0.f;
        #pragma unroll
        for (int c = 0; c < PCHUNKS; c++)
            sv += Pp[(size_t)c * PSZ + (size_t)m0 * NRANK + i];
        Ps[i] = sv;
    }
    for (int i = tid; i < 4 * 128 * NRANK; i += 256) {
        int g = i >> 10, j = (i >> 3) & 127, r = i & 7;
        int bg = (m0 >> 5) + g;
        int o = ND * NRANK + (n0 + j) * NRANK + r;
        size_t go = (size_t)bg * NW2 + o;
        xbs[r * XBP + g * 128 + j] =
            __half2float(xwpart[go]) + __half2float(xwpart[(size_t)NB * NW2 + go]) + b2[o];
    }
    __syncthreads();

    #pragma unroll 1
    for (int it = 0; it < 16; it++) {
        int idx = tid + it * 256;          // 0..4095
        int row = idx >> 5, c4 = idx & 31;
        int m = m0 + row;
        int g = row >> 5;
        const float4* pr = reinterpret_cast<const float4*>(Ps + row * 8);
        float4 p0 = pr[0], p1 = pr[1];
        float pw[8] = { p0.x, p0.y, p0.z, p0.w, p1.x, p1.y, p1.z, p1.w };
        float4 e = make_float4(0.f, 0.f, 0.f, 0.f);
        #pragma unroll
        for (int r = 0; r < 8; r++) {
            float4 xb = *reinterpret_cast<const float4*>(&xbs[r * XBP + g * 128 + c4 * 4]);
            e.x += pw[r] * xb.x; e.y += pw[r] * xb.y;
            e.z += pw[r] * xb.z; e.w += pw[r] * xb.w;
        }
        float4* po = reinterpret_cast<float4*>(out + (size_t)m * ND + n0 + c4 * 4);
        float4 v = *po;
        v.x += e.x; v.y += e.y; v.z += e.z; v.w += e.w;
        *po = v;
    }
}

// ---------------------------------------------------------------------------
#define G1_SMEM (4 * STG32)   // 108544

extern "C" void kernel_launch(void* const* d_in, const int* in_sizes, int n_in,
                              void* d_out, int out_size)
{
    const float* x    = (const float*)d_in[0];
    const float* ada  = (const float*)d_in[1];
    const float* base = (const float*)d_in[2];
    const float* w1   = (const float*)d_in[3];
    const float* b1   = (const float*)d_in[4];
    const float* w2   = (const float*)d_in[5];
    const float* b2   = (const float*)d_in[6];
    const float* ln_g = (const float*)d_in[7];
    const float* ln_b = (const float*)d_in[8];
    float* out = (float*)d_out;

    __half *ae, *h, *x16, *base16, *hpart16, *xwpart16;
    float *Pp;
    cudaGetSymbolAddress((void**)&ae, g_ae);
    cudaGetSymbolAddress((void**)&h,  g_h);
    cudaGetSymbolAddress((void**)&x16, g_x16);
    cudaGetSymbolAddress((void**)&base16, g_base16);
    cudaGetSymbolAddress((void**)&hpart16, g_hpart16);
    cudaGetSymbolAddress((void**)&xwpart16, g_xwpart16);
    cudaGetSymbolAddress((void**)&Pp, g_Ppart);

    cudaFuncSetAttribute((const void*)g1_kernel,
                         cudaFuncAttributeMaxDynamicSharedMemorySize, G1_SMEM);
    cudaFuncSetAttribute((const void*)fused_kernel,
                         cudaFuncAttributeMaxDynamicSharedMemorySize, FSMEM);

    // fused prep: cvt(x, base) + layernorm
    int n4x = NB * NT * ND / 4, n4b = ND * ND / 4;
    int ncvt = (n4x + n4b + 255) / 256;
    prep_kernel<<<ncvt + NB, 256>>>(
        (const float4*)x, x16, n4x, (const float4*)base, base16, n4x + n4b, ncvt,
        ada, ln_g, ln_b, ae);

    // hypernetwork G1 + reduce
    g1_kernel<<<dim3(NINTER / 128, 1, KSPLIT), 256, G1_SMEM>>>(ae, w1, hpart16);
    reduce_gelu16_kernel<<<NB * NINTER / 2 / 256, 256>>>(
        (const __half2*)hpart16, b1, h);

    // FUSED: G2 (odd) + final mainloop (even)
    fused_kernel<<<512, 256, FSMEM>>>(h, w2, xwpart16, x16, base16, out, x);

    // low-rank path + deferred LoRA add
    p_mma_kernel<<<dim3(NB, PCHUNKS), 256>>>(x16, xwpart16, b2, Pp);
    lora_add_kernel<<<dim3(ND / 128, NB * NT / BM), 256>>>(out, Pp, xwpart16, b2);
}